// round 1
// baseline (speedup 1.0000x reference)
#include <cuda_runtime.h>
#include <math.h>

#define NN   262144   // nodes
#define HH   256      // hidden
#define NV   65536    // vars
#define NP   8        // props
#define NG   512      // graphs
#define NHID 64       // gate hidden

#define BM 64
#define BK 16

__device__ float g_sums[NG * HH];
__device__ float g_maxs[NG * HH];
__device__ float g_gate[NV];
__device__ int   g_counts[NG];

// ---------------------------------------------------------------- init
__global__ void init_kernel() {
    int i = blockIdx.x * blockDim.x + threadIdx.x;
    if (i < NG * HH) {
        g_sums[i] = 0.0f;
        g_maxs[i] = -INFINITY;
    }
}

// ---------------------------------------------------------------- gate MLP
__global__ __launch_bounds__(256) void gate_kernel(
    const float* __restrict__ props,
    const float* __restrict__ W1, const float* __restrict__ b1,
    const float* __restrict__ W2, const float* __restrict__ b2)
{
    __shared__ float sW1[NP * NHID];
    __shared__ float sb1[NHID];
    __shared__ float sW2[NHID];
    int tid = threadIdx.x;
    for (int i = tid; i < NP * NHID; i += 256) sW1[i] = W1[i];
    if (tid < NHID) { sb1[tid] = b1[tid]; sW2[tid] = W2[tid]; }
    __syncthreads();

    int v = blockIdx.x * 256 + tid;
    if (v >= NV) return;
    float4 p0 = ((const float4*)props)[v * 2 + 0];
    float4 p1 = ((const float4*)props)[v * 2 + 1];
    float pr[NP] = {p0.x, p0.y, p0.z, p0.w, p1.x, p1.y, p1.z, p1.w};

    float acc = b2[0];
    #pragma unroll 4
    for (int j = 0; j < NHID; j++) {
        float s = sb1[j];
        #pragma unroll
        for (int p = 0; p < NP; p++) s += pr[p] * sW1[p * NHID + j];
        s = fmaxf(s, 0.0f);
        acc += s * sW2[j];
    }
    g_gate[v] = 1.0f / (1.0f + expf(-acc));
}

// ---------------------------------------------------------------- counts
__global__ void counts_kernel(const int* __restrict__ batch) {
    int g = blockIdx.x * blockDim.x + threadIdx.x;
    if (g >= NG) return;
    int lo = 0, hi = NN;
    while (lo < hi) { int mid = (lo + hi) >> 1; if (batch[mid] < g) lo = mid + 1; else hi = mid; }
    int start = lo;
    lo = 0; hi = NN;
    while (lo < hi) { int mid = (lo + hi) >> 1; if (batch[mid] <= g) lo = mid + 1; else hi = mid; }
    g_counts[g] = lo - start;
}

// ---------------------------------------------------------------- float atomic max
__device__ __forceinline__ void atomicMaxF(float* addr, float v) {
    if (v >= 0.0f) atomicMax((int*)addr, __float_as_int(v));
    else           atomicMin((unsigned int*)addr, __float_as_uint(v));
}

// ---------------------------------------------------------------- main GEMM + segment reduce
__global__ __launch_bounds__(256) void main_kernel(
    const float* __restrict__ emb,
    const int*   __restrict__ batch,
    const int*   __restrict__ ntype,
    const float* __restrict__ Wpre,
    const float* __restrict__ bpre)
{
    __shared__ float As[BM][BK + 1];     // 64 x 17
    __shared__ float Bs[BK][HH];         // 16 x 256
    __shared__ float red[8][HH];         // 8 x 256 reduction buffer
    __shared__ float wrow[BM];
    __shared__ int   brow[BM];

    int tid = threadIdx.x;
    int m0 = blockIdx.x * BM;
    int tx = tid & 31;   // col group: cols tx*8 .. +8
    int ty = tid >> 5;   // row group: rows ty*8 .. +8

    if (tid < BM) {
        int m = m0 + tid;
        brow[tid] = batch[m];
        float w = 1.0f;
        if (ntype[m] == 0) w = g_gate[m >> 2];
        wrow[tid] = w;
    }

    float acc[8][8];
    #pragma unroll
    for (int i = 0; i < 8; i++)
        #pragma unroll
        for (int j = 0; j < 8; j++) acc[i][j] = 0.0f;

    int arow = tid >> 2;            // 0..63
    int aseg = (tid & 3) * 4;       // 0,4,8,12
    int brw  = tid >> 6;            // 0..3
    int bcol = (tid & 63) * 4;      // 0..252

    for (int kt = 0; kt < HH; kt += BK) {
        float4 av = *(const float4*)&emb[(size_t)(m0 + arow) * HH + kt + aseg];
        As[arow][aseg + 0] = av.x;
        As[arow][aseg + 1] = av.y;
        As[arow][aseg + 2] = av.z;
        As[arow][aseg + 3] = av.w;
        #pragma unroll
        for (int i = 0; i < 4; i++) {
            int r = brw + i * 4;
            float4 bv = *(const float4*)&Wpre[(size_t)(kt + r) * HH + bcol];
            *(float4*)&Bs[r][bcol] = bv;
        }
        __syncthreads();

        #pragma unroll
        for (int k = 0; k < BK; k++) {
            float a[8], b[8];
            #pragma unroll
            for (int i = 0; i < 8; i++) a[i] = As[ty * 8 + i][k];
            float4 bv0 = *(float4*)&Bs[k][tx * 8];
            float4 bv1 = *(float4*)&Bs[k][tx * 8 + 4];
            b[0] = bv0.x; b[1] = bv0.y; b[2] = bv0.z; b[3] = bv0.w;
            b[4] = bv1.x; b[5] = bv1.y; b[6] = bv1.z; b[7] = bv1.w;
            #pragma unroll
            for (int i = 0; i < 8; i++)
                #pragma unroll
                for (int j = 0; j < 8; j++)
                    acc[i][j] = fmaf(a[i], b[j], acc[i][j]);
        }
        __syncthreads();
    }

    // bias + per-node gate weight
    #pragma unroll
    for (int j = 0; j < 8; j++) {
        float bb = bpre[tx * 8 + j];
        #pragma unroll
        for (int i = 0; i < 8; i++)
            acc[i][j] = (acc[i][j] + bb) * wrow[ty * 8 + i];
    }

    // segment reduce within block (tile usually spans 1-2 graphs)
    int glo = brow[0];
    int ghi = brow[BM - 1];
    for (int g = glo; g <= ghi; g++) {
        // --- sum ---
        float ps[8];
        #pragma unroll
        for (int j = 0; j < 8; j++) ps[j] = 0.0f;
        #pragma unroll
        for (int i = 0; i < 8; i++) {
            if (brow[ty * 8 + i] == g) {
                #pragma unroll
                for (int j = 0; j < 8; j++) ps[j] += acc[i][j];
            }
        }
        #pragma unroll
        for (int j = 0; j < 8; j++) red[ty][tx * 8 + j] = ps[j];
        __syncthreads();
        {
            float s = 0.0f;
            #pragma unroll
            for (int t = 0; t < 8; t++) s += red[t][tid];
            atomicAdd(&g_sums[g * HH + tid], s);
        }
        __syncthreads();
        // --- max ---
        float pm[8];
        #pragma unroll
        for (int j = 0; j < 8; j++) pm[j] = -INFINITY;
        #pragma unroll
        for (int i = 0; i < 8; i++) {
            if (brow[ty * 8 + i] == g) {
                #pragma unroll
                for (int j = 0; j < 8; j++) pm[j] = fmaxf(pm[j], acc[i][j]);
            }
        }
        #pragma unroll
        for (int j = 0; j < 8; j++) red[ty][tx * 8 + j] = pm[j];
        __syncthreads();
        {
            float mx = -INFINITY;
            #pragma unroll
            for (int t = 0; t < 8; t++) mx = fmaxf(mx, red[t][tid]);
            if (mx > -INFINITY) atomicMaxF(&g_maxs[g * HH + tid], mx);
        }
        __syncthreads();
    }
}

// ---------------------------------------------------------------- final linear
__global__ __launch_bounds__(256) void final_kernel(
    const float* __restrict__ Wpost,
    const float* __restrict__ bpost,
    float* __restrict__ out)
{
    __shared__ float comb[8][2 * HH];   // 8 graphs x 512
    __shared__ float invc[8];
    int tid = threadIdx.x;
    int g0 = blockIdx.x * 8;

    if (tid < 8) {
        int c = g_counts[g0 + tid];
        invc[tid] = 1.0f / fmaxf((float)c, 1.0f);
    }
    __syncthreads();

    for (int idx = tid; idx < 8 * 2 * HH; idx += 256) {
        int g = idx >> 9;
        int k = idx & 511;
        float v;
        if (k < HH) {
            v = g_sums[(size_t)(g0 + g) * HH + k] * invc[g];
        } else {
            float m = g_maxs[(size_t)(g0 + g) * HH + (k - HH)];
            v = isfinite(m) ? m : 0.0f;
        }
        comb[g][k] = v;
    }
    __syncthreads();

    float acc[8];
    #pragma unroll
    for (int g = 0; g < 8; g++) acc[g] = 0.0f;

    for (int k = 0; k < 2 * HH; k++) {
        float wv = Wpost[(size_t)k * HH + tid];
        #pragma unroll
        for (int g = 0; g < 8; g++) acc[g] = fmaf(comb[g][k], wv, acc[g]);
    }
    float bb = bpost[tid];
    #pragma unroll
    for (int g = 0; g < 8; g++)
        out[(size_t)(g0 + g) * HH + tid] = acc[g] + bb;
}

// ---------------------------------------------------------------- launch
extern "C" void kernel_launch(void* const* d_in, const int* in_sizes, int n_in,
                              void* d_out, int out_size)
{
    const float* emb   = (const float*)d_in[0];
    const int*   batch = (const int*)  d_in[1];
    const float* props = (const float*)d_in[2];
    const int*   ntype = (const int*)  d_in[3];
    const float* Wpre  = (const float*)d_in[4];
    const float* bpre  = (const float*)d_in[5];
    const float* W1    = (const float*)d_in[6];
    const float* b1    = (const float*)d_in[7];
    const float* W2    = (const float*)d_in[8];
    const float* b2    = (const float*)d_in[9];
    const float* Wpost = (const float*)d_in[10];
    const float* bpost = (const float*)d_in[11];
    float* out = (float*)d_out;

    init_kernel<<<(NG * HH + 255) / 256, 256>>>();
    gate_kernel<<<NV / 256, 256>>>(props, W1, b1, W2, b2);
    counts_kernel<<<(NG + 255) / 256, 256>>>(batch);
    main_kernel<<<NN / BM, 256>>>(emb, batch, ntype, Wpre, bpre);
    final_kernel<<<NG / 8, 256>>>(Wpost, bpost, out);
}

// round 3
// speedup vs baseline: 3.0314x; 3.0314x over previous
#include <cuda_runtime.h>
#include <cuda_fp16.h>
#include <math.h>
#include <stdint.h>

#define NN   262144
#define HH   256
#define NV   65536
#define NG   512
#define NP   8
#define NHID 64

#define BM 64
#define BK 32

// ---------------- device globals ----------------
__device__ float  g_sums[NG * HH];
__device__ float  g_maxs[NG * HH];
__device__ float  g_gate[NV];
__device__ int    g_counts[NG];
__device__ __half g_Wt[HH * HH];    // W_pre transposed: Wt[n][k], fp16

// ---------------- helpers ----------------
__device__ __forceinline__ uint32_t smem_u32(const void* p) {
    uint32_t a;
    asm("{ .reg .u64 t; cvta.to.shared.u64 t, %1; cvt.u32.u64 %0, t; }" : "=r"(a) : "l"(p));
    return a;
}
__device__ __forceinline__ void cp16(uint32_t dst, const void* src) {
    asm volatile("cp.async.cg.shared.global [%0], [%1], 16;" :: "r"(dst), "l"(src));
}
__device__ __forceinline__ void atomicMaxF(float* addr, float v) {
    if (v >= 0.0f) atomicMax((int*)addr, __float_as_int(v));
    else           atomicMin((unsigned int*)addr, __float_as_uint(v));
}
#define LDMX4(r0,r1,r2,r3,addr) \
    asm volatile("ldmatrix.sync.aligned.m8n8.x4.shared.b16 {%0,%1,%2,%3}, [%4];" \
                 : "=r"(r0), "=r"(r1), "=r"(r2), "=r"(r3) : "r"(addr))
#define MMA16816(c0,c1,c2,c3,a0,a1,a2,a3,b0,b1) \
    asm volatile("mma.sync.aligned.m16n8k16.row.col.f32.f16.f16.f32 " \
                 "{%0,%1,%2,%3}, {%4,%5,%6,%7}, {%8,%9}, {%0,%1,%2,%3};" \
                 : "+f"(c0), "+f"(c1), "+f"(c2), "+f"(c3) \
                 : "r"(a0), "r"(a1), "r"(a2), "r"(a3), "r"(b0), "r"(b1))

// ---------------- prep: init + gate MLP + counts + W transpose/convert ----------------
__global__ __launch_bounds__(256) void prep_kernel(
    const float* __restrict__ props,
    const float* __restrict__ W1, const float* __restrict__ b1,
    const float* __restrict__ W2, const float* __restrict__ b2,
    const float* __restrict__ Wpre,
    const int*   __restrict__ batch)
{
    __shared__ float sW1[NP * NHID];
    __shared__ float sb1[NHID];
    __shared__ float sW2[NHID];
    int tid = threadIdx.x;
    for (int i = tid; i < NP * NHID; i += 256) sW1[i] = W1[i];
    if (tid < NHID) { sb1[tid] = b1[tid]; sW2[tid] = W2[tid]; }
    __syncthreads();

    int idx = blockIdx.x * 256 + tid;     // 0..65535

    g_sums[idx] = 0.0f;          g_sums[idx + 65536] = 0.0f;
    g_maxs[idx] = -INFINITY;     g_maxs[idx + 65536] = -INFINITY;

    // Wt[n][k] = Wpre[k][n]
    {
        int k = idx >> 8, n = idx & 255;
        g_Wt[n * 256 + k] = __float2half(Wpre[idx]);
    }

    // gate MLP (one variable per thread)
    {
        float4 p0 = ((const float4*)props)[idx * 2 + 0];
        float4 p1 = ((const float4*)props)[idx * 2 + 1];
        float pr[NP] = {p0.x, p0.y, p0.z, p0.w, p1.x, p1.y, p1.z, p1.w};
        float acc = b2[0];
        #pragma unroll 4
        for (int j = 0; j < NHID; j++) {
            float s = sb1[j];
            #pragma unroll
            for (int p = 0; p < NP; p++) s += pr[p] * sW1[p * NHID + j];
            s = fmaxf(s, 0.0f);
            acc += s * sW2[j];
        }
        g_gate[idx] = 1.0f / (1.0f + expf(-acc));
    }

    if (idx < NG) {
        int g = idx;
        int lo = 0, hi = NN;
        while (lo < hi) { int mid = (lo + hi) >> 1; if (batch[mid] < g) lo = mid + 1; else hi = mid; }
        int start = lo;
        lo = 0; hi = NN;
        while (lo < hi) { int mid = (lo + hi) >> 1; if (batch[mid] <= g) lo = mid + 1; else hi = mid; }
        g_counts[g] = lo - start;
    }
}

// ---------------- main: HMMA GEMM + fused segment reduce ----------------
// smem (dynamic, 68608 B):
//  [0, 10240)       A bufs: 2 x 64 rows x 40 halfs (80 B/row)
//  [10240, 51200)   B bufs: 2 x 256 rows x 40 halfs
//  [0, 66560)       epilogue overlay: 8 warps x 32 x 65 floats
//  [66560, 68096)   brow[64] | wrow[64] | sbias[256]
#define OFF_B    10240
#define OFF_MISC 66560
#define SMEM_SZ  68608

__global__ __launch_bounds__(256, 2) void main_kernel(
    const float* __restrict__ emb,
    const int*   __restrict__ batch,
    const int*   __restrict__ ntype,
    const float* __restrict__ bpre)
{
    extern __shared__ char sm[];
    const uint32_t sbase = smem_u32(sm);
    int*   brow  = (int*)  (sm + OFF_MISC);
    float* wrow  = (float*)(sm + OFF_MISC + 256);
    float* sbias = (float*)(sm + OFF_MISC + 512);

    const int tid  = threadIdx.x;
    const int wid  = tid >> 5;
    const int lane = tid & 31;
    const int wm   = wid >> 2;       // 0..1  (32 rows each)
    const int wn   = wid & 3;        // 0..3  (64 cols each)
    const int m0   = blockIdx.x * BM;

    if (tid < BM) {
        int m = m0 + tid;
        brow[tid] = batch[m];
        float w = 1.0f;
        if (ntype[m] == 0) w = g_gate[m >> 2];
        wrow[tid] = w;
    }
    sbias[tid] = bpre[tid];

    // A gmem/STS addressing: thread handles row=tid>>2, 8 floats at seg=(tid&3)*8
    const int arow = tid >> 2;
    const int aseg = (tid & 3) * 8;
    const uint32_t a_sts = sbase + (uint32_t)(arow * 80 + aseg * 2);

    // B cp.async addressing: 4 rows-of-16B per thread
    // u = tid + i*256: n=u>>2, seg=u&3
    // ldmatrix lane offsets
    const uint32_t a_lm = sbase +
        (uint32_t)(((wm * 32 + (lane & 15)) * 40 + (lane >> 4) * 8) * 2);
    const uint32_t b_lm = sbase + OFF_B +
        (uint32_t)(((wn * 64 + (lane >> 4) * 8 + (lane & 7)) * 40 + ((lane >> 3) & 1) * 8) * 2);

    float acc[2][8][4];
    #pragma unroll
    for (int mi = 0; mi < 2; mi++)
        #pragma unroll
        for (int ni = 0; ni < 8; ni++)
            #pragma unroll
            for (int r = 0; r < 4; r++) acc[mi][ni][r] = 0.0f;

    // ---- prologue: chunk 0 ----
    {
        #pragma unroll
        for (int i = 0; i < 4; i++) {
            int u = tid + i * 256;
            int n = u >> 2, seg = u & 3;
            cp16(sbase + OFF_B + (uint32_t)(n * 80 + seg * 16),
                 (const char*)g_Wt + (size_t)n * 512 + seg * 16);
        }
        asm volatile("cp.async.commit_group;" ::: "memory");
        const float4* p = (const float4*)&emb[(size_t)(m0 + arow) * HH + aseg];
        float4 a0 = p[0], a1 = p[1];
        __half2 h0 = __float22half2_rn(make_float2(a0.x, a0.y));
        __half2 h1 = __float22half2_rn(make_float2(a0.z, a0.w));
        __half2 h2 = __float22half2_rn(make_float2(a1.x, a1.y));
        __half2 h3 = __float22half2_rn(make_float2(a1.z, a1.w));
        asm volatile("st.shared.v4.b32 [%0], {%1,%2,%3,%4};" :: "r"(a_sts),
                     "r"(*(uint32_t*)&h0), "r"(*(uint32_t*)&h1),
                     "r"(*(uint32_t*)&h2), "r"(*(uint32_t*)&h3) : "memory");
    }

    for (int c = 0; c < 8; c++) {
        const int buf  = c & 1;
        const int nbuf = buf ^ 1;
        asm volatile("cp.async.wait_group 0;" ::: "memory");
        __syncthreads();

        float4 a0, a1;
        if (c < 7) {
            // issue next B chunk
            #pragma unroll
            for (int i = 0; i < 4; i++) {
                int u = tid + i * 256;
                int n = u >> 2, seg = u & 3;
                cp16(sbase + OFF_B + (uint32_t)(nbuf * 20480 + n * 80 + seg * 16),
                     (const char*)g_Wt + (size_t)n * 512 + (c + 1) * 64 + seg * 16);
            }
            asm volatile("cp.async.commit_group;" ::: "memory");
            // issue next A loads (consumed after compute)
            const float4* p = (const float4*)&emb[(size_t)(m0 + arow) * HH + (c + 1) * BK + aseg];
            a0 = p[0]; a1 = p[1];
        }

        // ---- compute chunk c ----
        const uint32_t abase = a_lm + buf * 5120;
        const uint32_t bbase = b_lm + buf * 20480;
        #pragma unroll
        for (int ks = 0; ks < 2; ks++) {
            uint32_t af[2][4];
            #pragma unroll
            for (int mi = 0; mi < 2; mi++)
                LDMX4(af[mi][0], af[mi][1], af[mi][2], af[mi][3],
                      abase + mi * 1280 + ks * 32);
            uint32_t bf[4][4];
            #pragma unroll
            for (int nip = 0; nip < 4; nip++)
                LDMX4(bf[nip][0], bf[nip][1], bf[nip][2], bf[nip][3],
                      bbase + nip * 1280 + ks * 32);
            #pragma unroll
            for (int mi = 0; mi < 2; mi++)
                #pragma unroll
                for (int ni = 0; ni < 8; ni++)
                    MMA16816(acc[mi][ni][0], acc[mi][ni][1], acc[mi][ni][2], acc[mi][ni][3],
                             af[mi][0], af[mi][1], af[mi][2], af[mi][3],
                             bf[ni >> 1][(ni & 1) * 2], bf[ni >> 1][(ni & 1) * 2 + 1]);
        }

        if (c < 7) {
            __half2 h0 = __float22half2_rn(make_float2(a0.x, a0.y));
            __half2 h1 = __float22half2_rn(make_float2(a0.z, a0.w));
            __half2 h2 = __float22half2_rn(make_float2(a1.x, a1.y));
            __half2 h3 = __float22half2_rn(make_float2(a1.z, a1.w));
            asm volatile("st.shared.v4.b32 [%0], {%1,%2,%3,%4};"
                         :: "r"(a_sts + (uint32_t)(nbuf * 5120)),
                            "r"(*(uint32_t*)&h0), "r"(*(uint32_t*)&h1),
                            "r"(*(uint32_t*)&h2), "r"(*(uint32_t*)&h3) : "memory");
        }
    }

    // ---- epilogue: bias + gate, per-warp segment reduce ----
    __syncthreads();   // everyone done with AB smem; overlay now safe
    float* hreg = (float*)(sm + wid * 8320);   // [32][65]

    #pragma unroll
    for (int mi = 0; mi < 2; mi++) {
        int r0 = mi * 16 + (lane >> 2);
        float w0 = wrow[wm * 32 + r0];
        float w1 = wrow[wm * 32 + r0 + 8];
        #pragma unroll
        for (int ni = 0; ni < 8; ni++) {
            int col = ni * 8 + 2 * (lane & 3);
            float b0 = sbias[wn * 64 + col];
            float b1 = sbias[wn * 64 + col + 1];
            hreg[r0 * 65 + col]           = (acc[mi][ni][0] + b0) * w0;
            hreg[r0 * 65 + col + 1]       = (acc[mi][ni][1] + b1) * w0;
            hreg[(r0 + 8) * 65 + col]     = (acc[mi][ni][2] + b0) * w1;
            hreg[(r0 + 8) * 65 + col + 1] = (acc[mi][ni][3] + b1) * w1;
        }
    }
    __syncwarp();

    const int glo = brow[wm * 32];
    const int ghi = brow[wm * 32 + 31];
    #pragma unroll
    for (int half = 0; half < 2; half++) {
        int scol = lane + half * 32;
        int gcol = wn * 64 + scol;
        for (int g = glo; g <= ghi; g++) {
            float ps = 0.0f, pm = -INFINITY;
            bool any = false;
            #pragma unroll 4
            for (int i = 0; i < 32; i++) {
                if (brow[wm * 32 + i] == g) {
                    float v = hreg[i * 65 + scol];
                    ps += v; pm = fmaxf(pm, v); any = true;
                }
            }
            if (any) {
                atomicAdd(&g_sums[g * HH + gcol], ps);
                atomicMaxF(&g_maxs[g * HH + gcol], pm);
            }
        }
    }
}

// ---------------- final linear ----------------
__global__ __launch_bounds__(256) void final_kernel(
    const float* __restrict__ Wpost,
    const float* __restrict__ bpost,
    float* __restrict__ out)
{
    __shared__ float comb[8][2 * HH];
    __shared__ float invc[8];
    int tid = threadIdx.x;
    int g0 = blockIdx.x * 8;

    if (tid < 8) {
        int c = g_counts[g0 + tid];
        invc[tid] = 1.0f / fmaxf((float)c, 1.0f);
    }
    __syncthreads();

    for (int idx = tid; idx < 8 * 2 * HH; idx += 256) {
        int g = idx >> 9;
        int k = idx & 511;
        float v;
        if (k < HH) {
            v = g_sums[(size_t)(g0 + g) * HH + k] * invc[g];
        } else {
            float m = g_maxs[(size_t)(g0 + g) * HH + (k - HH)];
            v = isfinite(m) ? m : 0.0f;
        }
        comb[g][k] = v;
    }
    __syncthreads();

    float acc[8];
    #pragma unroll
    for (int g = 0; g < 8; g++) acc[g] = 0.0f;

    for (int k = 0; k < 2 * HH; k++) {
        float wv = Wpost[(size_t)k * HH + tid];
        #pragma unroll
        for (int g = 0; g < 8; g++) acc[g] = fmaf(comb[g][k], wv, acc[g]);
    }
    float bb = bpost[tid];
    #pragma unroll
    for (int g = 0; g < 8; g++)
        out[(size_t)(g0 + g) * HH + tid] = acc[g] + bb;
}

// ---------------- launch ----------------
extern "C" void kernel_launch(void* const* d_in, const int* in_sizes, int n_in,
                              void* d_out, int out_size)
{
    const float* emb   = (const float*)d_in[0];
    const int*   batch = (const int*)  d_in[1];
    const float* props = (const float*)d_in[2];
    const int*   ntype = (const int*)  d_in[3];
    const float* Wpre  = (const float*)d_in[4];
    const float* bpre  = (const float*)d_in[5];
    const float* W1    = (const float*)d_in[6];
    const float* b1    = (const float*)d_in[7];
    const float* W2    = (const float*)d_in[8];
    const float* b2    = (const float*)d_in[9];
    const float* Wpost = (const float*)d_in[10];
    const float* bpost = (const float*)d_in[11];
    float* out = (float*)d_out;

    cudaFuncSetAttribute(main_kernel, cudaFuncAttributeMaxDynamicSharedMemorySize, SMEM_SZ);

    prep_kernel<<<256, 256>>>(props, W1, b1, W2, b2, Wpre, batch);
    main_kernel<<<NN / BM, 256, SMEM_SZ>>>(emb, batch, ntype, bpre);
    final_kernel<<<NG / 8, 256>>>(Wpost, bpost, out);
}

// round 4
// speedup vs baseline: 3.0787x; 1.0156x over previous
#include <cuda_runtime.h>
#include <cuda_fp16.h>
#include <math.h>
#include <stdint.h>

#define NN   262144
#define HH   256
#define NV   65536
#define NG   512
#define NP   8
#define NHID 64

#define BM 64
#define BK 32

// ---------------- device globals ----------------
__device__ float  g_sums[NG * HH];
__device__ float  g_maxs[NG * HH];
__device__ float  g_gate[NV];
__device__ int    g_counts[NG];
__device__ __half g_Wt[HH * HH];    // W_pre transposed: Wt[n][k], fp16

// ---------------- helpers ----------------
__device__ __forceinline__ uint32_t smem_u32(const void* p) {
    uint32_t a;
    asm("{ .reg .u64 t; cvta.to.shared.u64 t, %1; cvt.u32.u64 %0, t; }" : "=r"(a) : "l"(p));
    return a;
}
__device__ __forceinline__ void cp16(uint32_t dst, const void* src) {
    asm volatile("cp.async.cg.shared.global [%0], [%1], 16;" :: "r"(dst), "l"(src));
}
__device__ __forceinline__ void atomicMaxF(float* addr, float v) {
    if (v >= 0.0f) atomicMax((int*)addr, __float_as_int(v));
    else           atomicMin((unsigned int*)addr, __float_as_uint(v));
}
#define LDMX4(r0,r1,r2,r3,addr) \
    asm volatile("ldmatrix.sync.aligned.m8n8.x4.shared.b16 {%0,%1,%2,%3}, [%4];" \
                 : "=r"(r0), "=r"(r1), "=r"(r2), "=r"(r3) : "r"(addr))
#define MMA16816(c0,c1,c2,c3,a0,a1,a2,a3,b0,b1) \
    asm volatile("mma.sync.aligned.m16n8k16.row.col.f32.f16.f16.f32 " \
                 "{%0,%1,%2,%3}, {%4,%5,%6,%7}, {%8,%9}, {%0,%1,%2,%3};" \
                 : "+f"(c0), "+f"(c1), "+f"(c2), "+f"(c3) \
                 : "r"(a0), "r"(a1), "r"(a2), "r"(a3), "r"(b0), "r"(b1))

// ---------------- prep: init + gate MLP + counts + W transpose/convert ----------------
__global__ __launch_bounds__(256) void prep_kernel(
    const float* __restrict__ props,
    const float* __restrict__ W1, const float* __restrict__ b1,
    const float* __restrict__ W2, const float* __restrict__ b2,
    const float* __restrict__ Wpre,
    const int*   __restrict__ batch)
{
    __shared__ float sW1[NP * NHID];
    __shared__ float sb1[NHID];
    __shared__ float sW2[NHID];
    int tid = threadIdx.x;
    for (int i = tid; i < NP * NHID; i += 256) sW1[i] = W1[i];
    if (tid < NHID) { sb1[tid] = b1[tid]; sW2[tid] = W2[tid]; }
    __syncthreads();

    int idx = blockIdx.x * 256 + tid;     // 0..65535

    g_sums[idx] = 0.0f;          g_sums[idx + 65536] = 0.0f;
    g_maxs[idx] = -INFINITY;     g_maxs[idx + 65536] = -INFINITY;

    // Wt[n][k] = Wpre[k][n]
    {
        int k = idx >> 8, n = idx & 255;
        g_Wt[n * 256 + k] = __float2half(Wpre[idx]);
    }

    // gate MLP (one variable per thread)
    {
        float4 p0 = ((const float4*)props)[idx * 2 + 0];
        float4 p1 = ((const float4*)props)[idx * 2 + 1];
        float pr[NP] = {p0.x, p0.y, p0.z, p0.w, p1.x, p1.y, p1.z, p1.w};
        float acc = b2[0];
        #pragma unroll 4
        for (int j = 0; j < NHID; j++) {
            float s = sb1[j];
            #pragma unroll
            for (int p = 0; p < NP; p++) s += pr[p] * sW1[p * NHID + j];
            s = fmaxf(s, 0.0f);
            acc += s * sW2[j];
        }
        g_gate[idx] = 1.0f / (1.0f + expf(-acc));
    }

    if (idx < NG) {
        int g = idx;
        int lo = 0, hi = NN;
        while (lo < hi) { int mid = (lo + hi) >> 1; if (batch[mid] < g) lo = mid + 1; else hi = mid; }
        int start = lo;
        lo = 0; hi = NN;
        while (lo < hi) { int mid = (lo + hi) >> 1; if (batch[mid] <= g) lo = mid + 1; else hi = mid; }
        g_counts[g] = lo - start;
    }
}

// ---------------- main: HMMA GEMM + fused segment reduce ----------------
// smem (dynamic, 68608 B):
//  [0, 10240)       A bufs: 2 x 64 rows x 40 halfs (80 B/row)
//  [10240, 51200)   B bufs: 2 x 256 rows x 40 halfs
//  [0, 66560)       epilogue overlay: 8 warps x 32 x 65 floats
//  [66560, 68096)   brow[64] | wrow[64] | sbias[256]
#define OFF_B    10240
#define OFF_MISC 66560
#define SMEM_SZ  68608

__global__ __launch_bounds__(256, 2) void main_kernel(
    const float* __restrict__ emb,
    const int*   __restrict__ batch,
    const int*   __restrict__ ntype,
    const float* __restrict__ bpre)
{
    extern __shared__ char sm[];
    const uint32_t sbase = smem_u32(sm);
    int*   brow  = (int*)  (sm + OFF_MISC);
    float* wrow  = (float*)(sm + OFF_MISC + 256);
    float* sbias = (float*)(sm + OFF_MISC + 512);

    const int tid  = threadIdx.x;
    const int wid  = tid >> 5;
    const int lane = tid & 31;
    const int wm   = wid >> 2;       // 0..1  (32 rows each)
    const int wn   = wid & 3;        // 0..3  (64 cols each)
    const int m0   = blockIdx.x * BM;

    if (tid < BM) {
        int m = m0 + tid;
        brow[tid] = batch[m];
        float w = 1.0f;
        if (ntype[m] == 0) w = g_gate[m >> 2];
        wrow[tid] = w;
    }
    sbias[tid] = bpre[tid];

    // A gmem/STS addressing: thread handles row=tid>>2, 8 floats at seg=(tid&3)*8
    const int arow = tid >> 2;
    const int aseg = (tid & 3) * 8;
    const uint32_t a_sts = sbase + (uint32_t)(arow * 80 + aseg * 2);

    // B cp.async addressing: 4 rows-of-16B per thread
    // u = tid + i*256: n=u>>2, seg=u&3
    // ldmatrix lane offsets
    const uint32_t a_lm = sbase +
        (uint32_t)(((wm * 32 + (lane & 15)) * 40 + (lane >> 4) * 8) * 2);
    const uint32_t b_lm = sbase + OFF_B +
        (uint32_t)(((wn * 64 + (lane >> 4) * 8 + (lane & 7)) * 40 + ((lane >> 3) & 1) * 8) * 2);

    float acc[2][8][4];
    #pragma unroll
    for (int mi = 0; mi < 2; mi++)
        #pragma unroll
        for (int ni = 0; ni < 8; ni++)
            #pragma unroll
            for (int r = 0; r < 4; r++) acc[mi][ni][r] = 0.0f;

    // ---- prologue: chunk 0 ----
    {
        #pragma unroll
        for (int i = 0; i < 4; i++) {
            int u = tid + i * 256;
            int n = u >> 2, seg = u & 3;
            cp16(sbase + OFF_B + (uint32_t)(n * 80 + seg * 16),
                 (const char*)g_Wt + (size_t)n * 512 + seg * 16);
        }
        asm volatile("cp.async.commit_group;" ::: "memory");
        const float4* p = (const float4*)&emb[(size_t)(m0 + arow) * HH + aseg];
        float4 a0 = p[0], a1 = p[1];
        __half2 h0 = __float22half2_rn(make_float2(a0.x, a0.y));
        __half2 h1 = __float22half2_rn(make_float2(a0.z, a0.w));
        __half2 h2 = __float22half2_rn(make_float2(a1.x, a1.y));
        __half2 h3 = __float22half2_rn(make_float2(a1.z, a1.w));
        asm volatile("st.shared.v4.b32 [%0], {%1,%2,%3,%4};" :: "r"(a_sts),
                     "r"(*(uint32_t*)&h0), "r"(*(uint32_t*)&h1),
                     "r"(*(uint32_t*)&h2), "r"(*(uint32_t*)&h3) : "memory");
    }

    for (int c = 0; c < 8; c++) {
        const int buf  = c & 1;
        const int nbuf = buf ^ 1;
        asm volatile("cp.async.wait_group 0;" ::: "memory");
        __syncthreads();

        float4 a0, a1;
        if (c < 7) {
            // issue next B chunk
            #pragma unroll
            for (int i = 0; i < 4; i++) {
                int u = tid + i * 256;
                int n = u >> 2, seg = u & 3;
                cp16(sbase + OFF_B + (uint32_t)(nbuf * 20480 + n * 80 + seg * 16),
                     (const char*)g_Wt + (size_t)n * 512 + (c + 1) * 64 + seg * 16);
            }
            asm volatile("cp.async.commit_group;" ::: "memory");
            // issue next A loads (consumed after compute)
            const float4* p = (const float4*)&emb[(size_t)(m0 + arow) * HH + (c + 1) * BK + aseg];
            a0 = p[0]; a1 = p[1];
        }

        // ---- compute chunk c ----
        const uint32_t abase = a_lm + buf * 5120;
        const uint32_t bbase = b_lm + buf * 20480;
        #pragma unroll
        for (int ks = 0; ks < 2; ks++) {
            uint32_t af[2][4];
            #pragma unroll
            for (int mi = 0; mi < 2; mi++)
                LDMX4(af[mi][0], af[mi][1], af[mi][2], af[mi][3],
                      abase + mi * 1280 + ks * 32);
            uint32_t bf[4][4];
            #pragma unroll
            for (int nip = 0; nip < 4; nip++)
                LDMX4(bf[nip][0], bf[nip][1], bf[nip][2], bf[nip][3],
                      bbase + nip * 1280 + ks * 32);
            #pragma unroll
            for (int mi = 0; mi < 2; mi++)
                #pragma unroll
                for (int ni = 0; ni < 8; ni++)
                    MMA16816(acc[mi][ni][0], acc[mi][ni][1], acc[mi][ni][2], acc[mi][ni][3],
                             af[mi][0], af[mi][1], af[mi][2], af[mi][3],
                             bf[ni >> 1][(ni & 1) * 2], bf[ni >> 1][(ni & 1) * 2 + 1]);
        }

        if (c < 7) {
            __half2 h0 = __float22half2_rn(make_float2(a0.x, a0.y));
            __half2 h1 = __float22half2_rn(make_float2(a0.z, a0.w));
            __half2 h2 = __float22half2_rn(make_float2(a1.x, a1.y));
            __half2 h3 = __float22half2_rn(make_float2(a1.z, a1.w));
            asm volatile("st.shared.v4.b32 [%0], {%1,%2,%3,%4};"
                         :: "r"(a_sts + (uint32_t)(nbuf * 5120)),
                            "r"(*(uint32_t*)&h0), "r"(*(uint32_t*)&h1),
                            "r"(*(uint32_t*)&h2), "r"(*(uint32_t*)&h3) : "memory");
        }
    }

    // ---- epilogue: bias + gate, per-warp segment reduce ----
    __syncthreads();   // everyone done with AB smem; overlay now safe
    float* hreg = (float*)(sm + wid * 8320);   // [32][65]

    #pragma unroll
    for (int mi = 0; mi < 2; mi++) {
        int r0 = mi * 16 + (lane >> 2);
        float w0 = wrow[wm * 32 + r0];
        float w1 = wrow[wm * 32 + r0 + 8];
        #pragma unroll
        for (int ni = 0; ni < 8; ni++) {
            int col = ni * 8 + 2 * (lane & 3);
            float b0 = sbias[wn * 64 + col];
            float b1 = sbias[wn * 64 + col + 1];
            hreg[r0 * 65 + col]           = (acc[mi][ni][0] + b0) * w0;
            hreg[r0 * 65 + col + 1]       = (acc[mi][ni][1] + b1) * w0;
            hreg[(r0 + 8) * 65 + col]     = (acc[mi][ni][2] + b0) * w1;
            hreg[(r0 + 8) * 65 + col + 1] = (acc[mi][ni][3] + b1) * w1;
        }
    }
    __syncwarp();

    const int glo = brow[wm * 32];
    const int ghi = brow[wm * 32 + 31];
    #pragma unroll
    for (int half = 0; half < 2; half++) {
        int scol = lane + half * 32;
        int gcol = wn * 64 + scol;
        for (int g = glo; g <= ghi; g++) {
            float ps = 0.0f, pm = -INFINITY;
            bool any = false;
            #pragma unroll 4
            for (int i = 0; i < 32; i++) {
                if (brow[wm * 32 + i] == g) {
                    float v = hreg[i * 65 + scol];
                    ps += v; pm = fmaxf(pm, v); any = true;
                }
            }
            if (any) {
                atomicAdd(&g_sums[g * HH + gcol], ps);
                atomicMaxF(&g_maxs[g * HH + gcol], pm);
            }
        }
    }
}

// ---------------- final linear ----------------
__global__ __launch_bounds__(256) void final_kernel(
    const float* __restrict__ Wpost,
    const float* __restrict__ bpost,
    float* __restrict__ out)
{
    __shared__ float comb[8][2 * HH];
    __shared__ float invc[8];
    int tid = threadIdx.x;
    int g0 = blockIdx.x * 8;

    if (tid < 8) {
        int c = g_counts[g0 + tid];
        invc[tid] = 1.0f / fmaxf((float)c, 1.0f);
    }
    __syncthreads();

    for (int idx = tid; idx < 8 * 2 * HH; idx += 256) {
        int g = idx >> 9;
        int k = idx & 511;
        float v;
        if (k < HH) {
            v = g_sums[(size_t)(g0 + g) * HH + k] * invc[g];
        } else {
            float m = g_maxs[(size_t)(g0 + g) * HH + (k - HH)];
            v = isfinite(m) ? m : 0.0f;
        }
        comb[g][k] = v;
    }
    __syncthreads();

    float acc[8];
    #pragma unroll
    for (int g = 0; g < 8; g++) acc[g] = 0.0f;

    for (int k = 0; k < 2 * HH; k++) {
        float wv = Wpost[(size_t)k * HH + tid];
        #pragma unroll
        for (int g = 0; g < 8; g++) acc[g] = fmaf(comb[g][k], wv, acc[g]);
    }
    float bb = bpost[tid];
    #pragma unroll
    for (int g = 0; g < 8; g++)
        out[(size_t)(g0 + g) * HH + tid] = acc[g] + bb;
}

// ---------------- launch ----------------
extern "C" void kernel_launch(void* const* d_in, const int* in_sizes, int n_in,
                              void* d_out, int out_size)
{
    const float* emb   = (const float*)d_in[0];
    const int*   batch = (const int*)  d_in[1];
    const float* props = (const float*)d_in[2];
    const int*   ntype = (const int*)  d_in[3];
    const float* Wpre  = (const float*)d_in[4];
    const float* bpre  = (const float*)d_in[5];
    const float* W1    = (const float*)d_in[6];
    const float* b1    = (const float*)d_in[7];
    const float* W2    = (const float*)d_in[8];
    const float* b2    = (const float*)d_in[9];
    const float* Wpost = (const float*)d_in[10];
    const float* bpost = (const float*)d_in[11];
    float* out = (float*)d_out;

    cudaFuncSetAttribute(main_kernel, cudaFuncAttributeMaxDynamicSharedMemorySize, SMEM_SZ);

    prep_kernel<<<256, 256>>>(props, W1, b1, W2, b2, Wpre, batch);
    main_kernel<<<NN / BM, 256, SMEM_SZ>>>(emb, batch, ntype, bpre);
    final_kernel<<<NG / 8, 256>>>(Wpost, bpost, out);
}

// round 5
// speedup vs baseline: 3.1788x; 1.0325x over previous
#include <cuda_runtime.h>
#include <cuda_fp16.h>
#include <math.h>
#include <stdint.h>

#define NN   262144
#define HH   256
#define NV   65536
#define NG   512
#define NP   8
#define NHID 64

#define BM 64
#define BK 32

// ---------------- device globals ----------------
__device__ float  g_sums[NG * HH];
__device__ float  g_maxs[NG * HH];
__device__ float  g_gate[NV];
__device__ int    g_counts[NG];
__device__ __half g_Wt[HH * HH];    // W_pre transposed: Wt[n][k], fp16

// ---------------- helpers ----------------
__device__ __forceinline__ uint32_t smem_u32(const void* p) {
    uint32_t a;
    asm("{ .reg .u64 t; cvta.to.shared.u64 t, %1; cvt.u32.u64 %0, t; }" : "=r"(a) : "l"(p));
    return a;
}
__device__ __forceinline__ void cp16(uint32_t dst, const void* src) {
    asm volatile("cp.async.cg.shared.global [%0], [%1], 16;" :: "r"(dst), "l"(src));
}
__device__ __forceinline__ void atomicMaxF(float* addr, float v) {
    if (v >= 0.0f) atomicMax((int*)addr, __float_as_int(v));
    else           atomicMin((unsigned int*)addr, __float_as_uint(v));
}
#define LDMX4(r0,r1,r2,r3,addr) \
    asm volatile("ldmatrix.sync.aligned.m8n8.x4.shared.b16 {%0,%1,%2,%3}, [%4];" \
                 : "=r"(r0), "=r"(r1), "=r"(r2), "=r"(r3) : "r"(addr))
#define MMA16816(c0,c1,c2,c3,a0,a1,a2,a3,b0,b1) \
    asm volatile("mma.sync.aligned.m16n8k16.row.col.f32.f16.f16.f32 " \
                 "{%0,%1,%2,%3}, {%4,%5,%6,%7}, {%8,%9}, {%0,%1,%2,%3};" \
                 : "+f"(c0), "+f"(c1), "+f"(c2), "+f"(c3) \
                 : "r"(a0), "r"(a1), "r"(a2), "r"(a3), "r"(b0), "r"(b1))

// ---------------- prep: init + gate MLP (ILP-4) + counts + W transpose ----------------
__global__ __launch_bounds__(256) void prep_kernel(
    const float* __restrict__ props,
    const float* __restrict__ W1, const float* __restrict__ b1,
    const float* __restrict__ W2, const float* __restrict__ b2,
    const float* __restrict__ Wpre,
    const int*   __restrict__ batch)
{
    __shared__ float sW1[NP * NHID];
    __shared__ float sb1[NHID];
    __shared__ float sW2[NHID];
    int tid = threadIdx.x;
    for (int i = tid; i < NP * NHID; i += 256) sW1[i] = W1[i];
    if (tid < NHID) { sb1[tid] = b1[tid]; sW2[tid] = W2[tid]; }
    __syncthreads();

    int idx = blockIdx.x * 256 + tid;     // 0..65535

    g_sums[idx] = 0.0f;          g_sums[idx + 65536] = 0.0f;
    g_maxs[idx] = -INFINITY;     g_maxs[idx + 65536] = -INFINITY;

    // Wt[n][k] = Wpre[k][n]
    {
        int k = idx >> 8, n = idx & 255;
        g_Wt[n * 256 + k] = __float2half(Wpre[idx]);
    }

    // gate MLP: 4 parallel hidden-unit chains + 2 accumulators
    {
        float4 p0 = ((const float4*)props)[idx * 2 + 0];
        float4 p1 = ((const float4*)props)[idx * 2 + 1];
        float pr[NP] = {p0.x, p0.y, p0.z, p0.w, p1.x, p1.y, p1.z, p1.w};
        float accA = b2[0], accB = 0.0f;
        #pragma unroll
        for (int j = 0; j < NHID; j += 4) {
            float s0 = sb1[j], s1 = sb1[j + 1], s2 = sb1[j + 2], s3 = sb1[j + 3];
            #pragma unroll
            for (int p = 0; p < NP; p++) {
                float pv = pr[p];
                const float* w = &sW1[p * NHID + j];
                s0 = fmaf(pv, w[0], s0);
                s1 = fmaf(pv, w[1], s1);
                s2 = fmaf(pv, w[2], s2);
                s3 = fmaf(pv, w[3], s3);
            }
            accA = fmaf(fmaxf(s0, 0.0f), sW2[j],     accA);
            accB = fmaf(fmaxf(s1, 0.0f), sW2[j + 1], accB);
            accA = fmaf(fmaxf(s2, 0.0f), sW2[j + 2], accA);
            accB = fmaf(fmaxf(s3, 0.0f), sW2[j + 3], accB);
        }
        g_gate[idx] = 1.0f / (1.0f + expf(-(accA + accB)));
    }

    if (idx < NG) {
        int g = idx;
        int lo = 0, hi = NN;
        while (lo < hi) { int mid = (lo + hi) >> 1; if (batch[mid] < g) lo = mid + 1; else hi = mid; }
        int start = lo;
        lo = 0; hi = NN;
        while (lo < hi) { int mid = (lo + hi) >> 1; if (batch[mid] <= g) lo = mid + 1; else hi = mid; }
        g_counts[g] = lo - start;
    }
}

// ---------------- main: HMMA GEMM, 3-stage pipeline + fused segment reduce ----------------
// smem (dynamic, 78336 B):
//  A stages: 3 x 5120      [0, 15360)
//  B stages: 3 x 20480     [15360, 76800)
//  epilogue overlay: 8 warps x 32 x 65 floats = 66560, aliases [0, 66560)
//  misc at 76800: brow[64] | wrow[64] | sbias[256]
#define OFF_B    15360
#define OFF_MISC 76800
#define SMEM_SZ  78336
#define A_STAGE  5120
#define B_STAGE  20480

__global__ __launch_bounds__(256, 2) void main_kernel(
    const float* __restrict__ emb,
    const int*   __restrict__ batch,
    const int*   __restrict__ ntype,
    const float* __restrict__ bpre)
{
    extern __shared__ char sm[];
    const uint32_t sbase = smem_u32(sm);
    int*   brow  = (int*)  (sm + OFF_MISC);
    float* wrow  = (float*)(sm + OFF_MISC + 256);
    float* sbias = (float*)(sm + OFF_MISC + 512);

    const int tid  = threadIdx.x;
    const int wid  = tid >> 5;
    const int lane = tid & 31;
    const int wm   = wid >> 2;       // 0..1  (32 rows each)
    const int wn   = wid & 3;        // 0..3  (64 cols each)
    const int m0   = blockIdx.x * BM;

    if (tid < BM) {
        int m = m0 + tid;
        brow[tid] = batch[m];
        float w = 1.0f;
        if (ntype[m] == 0) w = g_gate[m >> 2];
        wrow[tid] = w;
    }
    sbias[tid] = bpre[tid];

    // A addressing: thread -> row = tid>>2, 8 floats at seg=(tid&3)*8
    const int arow = tid >> 2;
    const int aseg = (tid & 3) * 8;
    const uint32_t a_sts = sbase + (uint32_t)(arow * 80 + aseg * 2);
    const float4* aptr = (const float4*)&emb[(size_t)(m0 + arow) * HH + aseg];

    // B cp.async: u = tid + i*256 -> n=u>>2, seg=u&3
    // ldmatrix lane offsets (proven R4 layout)
    const uint32_t a_lm = sbase +
        (uint32_t)(((wm * 32 + (lane & 15)) * 40 + (lane >> 4) * 8) * 2);
    const uint32_t b_lm = sbase + OFF_B +
        (uint32_t)(((wn * 64 + (lane >> 4) * 8 + (lane & 7)) * 40 + ((lane >> 3) & 1) * 8) * 2);

    float acc[2][8][4];
    #pragma unroll
    for (int mi = 0; mi < 2; mi++)
        #pragma unroll
        for (int ni = 0; ni < 8; ni++)
            #pragma unroll
            for (int r = 0; r < 4; r++) acc[mi][ni][r] = 0.0f;

    // B issue helper values
    const int bn   = (tid) >> 2;          // reused per i via u
    (void)bn;

    float4 ra[2][2];   // A prefetch regs: ra[parity][2]

    // ---- prologue ----
    // B0 -> stage0
    #pragma unroll
    for (int i = 0; i < 4; i++) {
        int u = tid + i * 256;
        int n = u >> 2, seg = u & 3;
        cp16(sbase + OFF_B + (uint32_t)(n * 80 + seg * 16),
             (const char*)g_Wt + (size_t)n * 512 + seg * 16);
    }
    asm volatile("cp.async.commit_group;" ::: "memory");
    // A0 -> regs -> stage0
    {
        float4 a0 = aptr[0], a1 = aptr[1];
        __half2 h0 = __float22half2_rn(make_float2(a0.x, a0.y));
        __half2 h1 = __float22half2_rn(make_float2(a0.z, a0.w));
        __half2 h2 = __float22half2_rn(make_float2(a1.x, a1.y));
        __half2 h3 = __float22half2_rn(make_float2(a1.z, a1.w));
        asm volatile("st.shared.v4.b32 [%0], {%1,%2,%3,%4};" :: "r"(a_sts),
                     "r"(*(uint32_t*)&h0), "r"(*(uint32_t*)&h1),
                     "r"(*(uint32_t*)&h2), "r"(*(uint32_t*)&h3) : "memory");
    }
    // B1 -> stage1
    #pragma unroll
    for (int i = 0; i < 4; i++) {
        int u = tid + i * 256;
        int n = u >> 2, seg = u & 3;
        cp16(sbase + OFF_B + (uint32_t)(B_STAGE + n * 80 + seg * 16),
             (const char*)g_Wt + (size_t)n * 512 + 64 + seg * 16);
    }
    asm volatile("cp.async.commit_group;" ::: "memory");
    // A1 -> regs (held)
    {
        const float4* p = (const float4*)((const char*)aptr + BK * 4);
        ra[1][0] = p[0]; ra[1][1] = p[1];
    }

    #pragma unroll
    for (int c = 0; c < 8; c++) {
        const int buf = c % 3;
        if (c < 7) { asm volatile("cp.async.wait_group 1;" ::: "memory"); }
        else       { asm volatile("cp.async.wait_group 0;" ::: "memory"); }
        __syncthreads();

        if (c <= 5) {
            // issue B(c+2) into stage (c+2)%3
            const uint32_t bdst = sbase + OFF_B + (uint32_t)(((c + 2) % 3) * B_STAGE);
            #pragma unroll
            for (int i = 0; i < 4; i++) {
                int u = tid + i * 256;
                int n = u >> 2, seg = u & 3;
                cp16(bdst + (uint32_t)(n * 80 + seg * 16),
                     (const char*)g_Wt + (size_t)n * 512 + (c + 2) * 64 + seg * 16);
            }
            asm volatile("cp.async.commit_group;" ::: "memory");
            // LDG A(c+2) -> regs
            const float4* p = (const float4*)((const char*)aptr + (size_t)(c + 2) * BK * 4);
            ra[c & 1][0] = p[0]; ra[c & 1][1] = p[1];
        }

        // ---- compute chunk c ----
        const uint32_t abase = a_lm + (uint32_t)(buf * A_STAGE);
        const uint32_t bbase = b_lm + (uint32_t)(buf * B_STAGE);
        #pragma unroll
        for (int ks = 0; ks < 2; ks++) {
            uint32_t af[2][4];
            #pragma unroll
            for (int mi = 0; mi < 2; mi++)
                LDMX4(af[mi][0], af[mi][1], af[mi][2], af[mi][3],
                      abase + mi * 1280 + ks * 32);
            uint32_t bf[4][4];
            #pragma unroll
            for (int nip = 0; nip < 4; nip++)
                LDMX4(bf[nip][0], bf[nip][1], bf[nip][2], bf[nip][3],
                      bbase + nip * 1280 + ks * 32);
            #pragma unroll
            for (int mi = 0; mi < 2; mi++)
                #pragma unroll
                for (int ni = 0; ni < 8; ni++)
                    MMA16816(acc[mi][ni][0], acc[mi][ni][1], acc[mi][ni][2], acc[mi][ni][3],
                             af[mi][0], af[mi][1], af[mi][2], af[mi][3],
                             bf[ni >> 1][(ni & 1) * 2], bf[ni >> 1][(ni & 1) * 2 + 1]);
        }

        if (c <= 6) {
            // STS A(c+1) from regs into stage (c+1)%3
            float4 a0 = ra[(c + 1) & 1][0], a1 = ra[(c + 1) & 1][1];
            __half2 h0 = __float22half2_rn(make_float2(a0.x, a0.y));
            __half2 h1 = __float22half2_rn(make_float2(a0.z, a0.w));
            __half2 h2 = __float22half2_rn(make_float2(a1.x, a1.y));
            __half2 h3 = __float22half2_rn(make_float2(a1.z, a1.w));
            asm volatile("st.shared.v4.b32 [%0], {%1,%2,%3,%4};"
                         :: "r"(a_sts + (uint32_t)(((c + 1) % 3) * A_STAGE)),
                            "r"(*(uint32_t*)&h0), "r"(*(uint32_t*)&h1),
                            "r"(*(uint32_t*)&h2), "r"(*(uint32_t*)&h3) : "memory");
        }
    }

    // ---- epilogue: bias + gate, per-warp segment reduce ----
    __syncthreads();   // all compute done; overlay safe
    float* hreg = (float*)(sm + wid * 8320);   // [32][65]

    #pragma unroll
    for (int mi = 0; mi < 2; mi++) {
        int r0 = mi * 16 + (lane >> 2);
        float w0 = wrow[wm * 32 + r0];
        float w1 = wrow[wm * 32 + r0 + 8];
        #pragma unroll
        for (int ni = 0; ni < 8; ni++) {
            int col = ni * 8 + 2 * (lane & 3);
            float b0 = sbias[wn * 64 + col];
            float b1 = sbias[wn * 64 + col + 1];
            hreg[r0 * 65 + col]           = (acc[mi][ni][0] + b0) * w0;
            hreg[r0 * 65 + col + 1]       = (acc[mi][ni][1] + b1) * w0;
            hreg[(r0 + 8) * 65 + col]     = (acc[mi][ni][2] + b0) * w1;
            hreg[(r0 + 8) * 65 + col + 1] = (acc[mi][ni][3] + b1) * w1;
        }
    }
    __syncwarp();

    const int glo = brow[wm * 32];
    const int ghi = brow[wm * 32 + 31];
    #pragma unroll
    for (int half = 0; half < 2; half++) {
        int scol = lane + half * 32;
        int gcol = wn * 64 + scol;
        for (int g = glo; g <= ghi; g++) {
            float ps = 0.0f, pm = -INFINITY;
            bool any = false;
            #pragma unroll 4
            for (int i = 0; i < 32; i++) {
                if (brow[wm * 32 + i] == g) {
                    float v = hreg[i * 65 + scol];
                    ps += v; pm = fmaxf(pm, v); any = true;
                }
            }
            if (any) {
                atomicAdd(&g_sums[g * HH + gcol], ps);
                atomicMaxF(&g_maxs[g * HH + gcol], pm);
            }
        }
    }
}

// ---------------- final linear ----------------
__global__ __launch_bounds__(256) void final_kernel(
    const float* __restrict__ Wpost,
    const float* __restrict__ bpost,
    float* __restrict__ out)
{
    __shared__ float comb[8][2 * HH];
    __shared__ float invc[8];
    int tid = threadIdx.x;
    int g0 = blockIdx.x * 8;

    if (tid < 8) {
        int c = g_counts[g0 + tid];
        invc[tid] = 1.0f / fmaxf((float)c, 1.0f);
    }
    __syncthreads();

    for (int idx = tid; idx < 8 * 2 * HH; idx += 256) {
        int g = idx >> 9;
        int k = idx & 511;
        float v;
        if (k < HH) {
            v = g_sums[(size_t)(g0 + g) * HH + k] * invc[g];
        } else {
            float m = g_maxs[(size_t)(g0 + g) * HH + (k - HH)];
            v = isfinite(m) ? m : 0.0f;
        }
        comb[g][k] = v;
    }
    __syncthreads();

    float acc[8];
    #pragma unroll
    for (int g = 0; g < 8; g++) acc[g] = 0.0f;

    for (int k = 0; k < 2 * HH; k++) {
        float wv = Wpost[(size_t)k * HH + tid];
        #pragma unroll
        for (int g = 0; g < 8; g++) acc[g] = fmaf(comb[g][k], wv, acc[g]);
    }
    float bb = bpost[tid];
    #pragma unroll
    for (int g = 0; g < 8; g++)
        out[(size_t)(g0 + g) * HH + tid] = acc[g] + bb;
}

// ---------------- launch ----------------
extern "C" void kernel_launch(void* const* d_in, const int* in_sizes, int n_in,
                              void* d_out, int out_size)
{
    const float* emb   = (const float*)d_in[0];
    const int*   batch = (const int*)  d_in[1];
    const float* props = (const float*)d_in[2];
    const int*   ntype = (const int*)  d_in[3];
    const float* Wpre  = (const float*)d_in[4];
    const float* bpre  = (const float*)d_in[5];
    const float* W1    = (const float*)d_in[6];
    const float* b1    = (const float*)d_in[7];
    const float* W2    = (const float*)d_in[8];
    const float* b2    = (const float*)d_in[9];
    const float* Wpost = (const float*)d_in[10];
    const float* bpost = (const float*)d_in[11];
    float* out = (float*)d_out;

    cudaFuncSetAttribute(main_kernel, cudaFuncAttributeMaxDynamicSharedMemorySize, SMEM_SZ);

    prep_kernel<<<256, 256>>>(props, W1, b1, W2, b2, Wpre, batch);
    main_kernel<<<NN / BM, 256, SMEM_SZ>>>(emb, batch, ntype, bpre);
    final_kernel<<<NG / 8, 256>>>(Wpost, bpost, out);
}

// round 6
// speedup vs baseline: 3.2235x; 1.0141x over previous
#include <cuda_runtime.h>
#include <cuda_fp16.h>
#include <math.h>
#include <stdint.h>

#define NN   262144
#define HH   256
#define NV   65536
#define NG   512
#define NP   8
#define NHID 64

#define NTILES    4096      // NN / 64
#define GRID_MAIN 148

// ---------------- device globals ----------------
__device__ float  g_sums[NG * HH];
__device__ float  g_maxs[NG * HH];
__device__ float  g_gate[NV];
__device__ int    g_start[NG + 1];
__device__ __half g_Wt[HH * HH];    // W_pre transposed: Wt[n][k], fp16

// ---------------- helpers ----------------
__device__ __forceinline__ uint32_t smem_u32(const void* p) {
    uint32_t a;
    asm("{ .reg .u64 t; cvta.to.shared.u64 t, %1; cvt.u32.u64 %0, t; }" : "=r"(a) : "l"(p));
    return a;
}
__device__ __forceinline__ void cp16(uint32_t dst, const void* src) {
    asm volatile("cp.async.cg.shared.global [%0], [%1], 16;" :: "r"(dst), "l"(src));
}
__device__ __forceinline__ void atomicMaxF(float* addr, float v) {
    if (v >= 0.0f) atomicMax((int*)addr, __float_as_int(v));
    else           atomicMin((unsigned int*)addr, __float_as_uint(v));
}
#define LDMX4(r0,r1,r2,r3,addr) \
    asm volatile("ldmatrix.sync.aligned.m8n8.x4.shared.b16 {%0,%1,%2,%3}, [%4];" \
                 : "=r"(r0), "=r"(r1), "=r"(r2), "=r"(r3) : "r"(addr))
#define MMA16816(c0,c1,c2,c3,a0,a1,a2,a3,b0,b1) \
    asm volatile("mma.sync.aligned.m16n8k16.row.col.f32.f16.f16.f32 " \
                 "{%0,%1,%2,%3}, {%4,%5,%6,%7}, {%8,%9}, {%0,%1,%2,%3};" \
                 : "+f"(c0), "+f"(c1), "+f"(c2), "+f"(c3) \
                 : "r"(a0), "r"(a1), "r"(a2), "r"(a3), "r"(b0), "r"(b1))

// ---------------- prep: init + gate MLP + segment boundaries + W transpose ----------------
__global__ __launch_bounds__(256) void prep_kernel(
    const float* __restrict__ props,
    const float* __restrict__ W1, const float* __restrict__ b1,
    const float* __restrict__ W2, const float* __restrict__ b2,
    const float* __restrict__ Wpre,
    const int*   __restrict__ batch)
{
    __shared__ float sW1[NP * NHID];
    __shared__ float sb1[NHID];
    __shared__ float sW2[NHID];
    int tid = threadIdx.x;
    for (int i = tid; i < NP * NHID; i += 256) sW1[i] = W1[i];
    if (tid < NHID) { sb1[tid] = b1[tid]; sW2[tid] = W2[tid]; }
    __syncthreads();

    int idx = blockIdx.x * 256 + tid;     // 0..65535

    g_sums[idx] = 0.0f;          g_sums[idx + 65536] = 0.0f;
    g_maxs[idx] = -INFINITY;     g_maxs[idx + 65536] = -INFINITY;

    // Wt[n][k] = Wpre[k][n]
    {
        int k = idx >> 8, n = idx & 255;
        g_Wt[n * 256 + k] = __float2half(Wpre[idx]);
    }

    // segment boundary scan: 4 nodes per thread (batch is sorted)
    {
        int i0 = idx * 4;
        int4 b4 = *(const int4*)&batch[i0];
        int v[4] = {b4.x, b4.y, b4.z, b4.w};
        int p = (i0 == 0) ? -1 : batch[i0 - 1];
        #pragma unroll
        for (int e = 0; e < 4; e++) {
            for (int g = p + 1; g <= v[e]; g++) g_start[g] = i0 + e;
            p = v[e];
        }
        if (i0 + 4 == NN)
            for (int g = v[3] + 1; g <= NG; g++) g_start[g] = NN;
    }

    // gate MLP: 4 parallel hidden-unit chains + 2 accumulators
    {
        float4 p0 = ((const float4*)props)[idx * 2 + 0];
        float4 p1 = ((const float4*)props)[idx * 2 + 1];
        float pr[NP] = {p0.x, p0.y, p0.z, p0.w, p1.x, p1.y, p1.z, p1.w};
        float accA = b2[0], accB = 0.0f;
        #pragma unroll
        for (int j = 0; j < NHID; j += 4) {
            float s0 = sb1[j], s1 = sb1[j + 1], s2 = sb1[j + 2], s3 = sb1[j + 3];
            #pragma unroll
            for (int p2i = 0; p2i < NP; p2i++) {
                float pv = pr[p2i];
                const float* w = &sW1[p2i * NHID + j];
                s0 = fmaf(pv, w[0], s0);
                s1 = fmaf(pv, w[1], s1);
                s2 = fmaf(pv, w[2], s2);
                s3 = fmaf(pv, w[3], s3);
            }
            accA = fmaf(fmaxf(s0, 0.0f), sW2[j],     accA);
            accB = fmaf(fmaxf(s1, 0.0f), sW2[j + 1], accB);
            accA = fmaf(fmaxf(s2, 0.0f), sW2[j + 2], accA);
            accB = fmaf(fmaxf(s3, 0.0f), sW2[j + 3], accB);
        }
        g_gate[idx] = 1.0f / (1.0f + expf(-(accA + accB)));
    }
}

// ---------------- main: persistent HMMA GEMM, B resident in smem ----------------
// smem layout (204800 B dynamic):
//   B:        [0, 135168)            256 rows x 264 halfs (stride 528 B)
//   A stages: [135168, 135168+2*33792)  2 x (64 rows x 264 halfs)
//   misc:     [202752, 204800)       brow[2][64] int | wrow[2][64] f | sbias[256] f
#define B_BYTES  135168
#define A_OFF    135168
#define A_STAGE  33792
#define MISC_OFF 202752
#define SMEM_SZ  204800

__global__ __launch_bounds__(512, 1) void main_kernel(
    const float* __restrict__ emb,
    const int*   __restrict__ batch,
    const int*   __restrict__ ntype,
    const float* __restrict__ bpre)
{
    extern __shared__ char sm[];
    const uint32_t sbase = smem_u32(sm);
    int*   brow  = (int*)  (sm + MISC_OFF);            // [2][64]
    float* wrow  = (float*)(sm + MISC_OFF + 512);      // [2][64]
    float* sbias = (float*)(sm + MISC_OFF + 1024);     // [256]

    const int tid  = threadIdx.x;
    const int wid  = tid >> 5;
    const int lane = tid & 31;
    const int wm   = wid >> 2;     // 0..3: rows [wm*16, +16)
    const int wn   = wid & 3;      // 0..3: cols [wn*64, +64)

    // ---- load B once (persistent, 135 KB) ----
    #pragma unroll
    for (int i = 0; i < 16; i++) {
        int u = tid + i * 512;         // 0..8191
        int n = u >> 5, kc = u & 31;
        cp16(sbase + (uint32_t)(n * 528 + kc * 16),
             (const char*)g_Wt + (size_t)n * 512 + kc * 16);
    }
    asm volatile("cp.async.commit_group;" ::: "memory");

    if (tid < 256) sbias[tid] = bpre[tid];

    const int arow = tid >> 3;     // 0..63
    const int aseg = tid & 7;      // float4 slot; col floats = j*32 + aseg*4

    // ---- prologue: tile t0 -> stage 0 ----
    const int t0 = blockIdx.x;
    float4 ra[8];
    {
        const float* ap = emb + (size_t)(t0 * 64 + arow) * HH + aseg * 4;
        #pragma unroll
        for (int j = 0; j < 8; j++) ra[j] = *(const float4*)(ap + j * 32);
    }
    if (tid < 64) {
        int m = t0 * 64 + tid;
        brow[tid] = batch[m];
        wrow[tid] = (ntype[m] == 0) ? g_gate[m >> 2] : 1.0f;
    }
    {
        uint32_t base = sbase + A_OFF + (uint32_t)((arow * 264 + aseg * 4) * 2);
        #pragma unroll
        for (int j = 0; j < 8; j++) {
            __half2 h0 = __float22half2_rn(make_float2(ra[j].x, ra[j].y));
            __half2 h1 = __float22half2_rn(make_float2(ra[j].z, ra[j].w));
            asm volatile("st.shared.v2.b32 [%0], {%1,%2};"
                         :: "r"(base + j * 64),
                            "r"(*(uint32_t*)&h0), "r"(*(uint32_t*)&h1) : "memory");
        }
    }
    asm volatile("cp.async.wait_group 0;" ::: "memory");
    __syncthreads();

    // ldmatrix lane addresses (stride 264 halfs = odd multiple of 8 -> conflict-free)
    const uint32_t a_lm = sbase + A_OFF +
        (uint32_t)(((wm * 16 + (lane & 15)) * 264 + (lane >> 4) * 8) * 2);
    const uint32_t b_lm = sbase +
        (uint32_t)(((wn * 64 + (lane >> 4) * 8 + (lane & 7)) * 264 + ((lane >> 3) & 1) * 8) * 2);

    for (int t = t0, it = 0; t < NTILES; t += GRID_MAIN, it++) {
        const int cur = it & 1;
        const int nt  = t + GRID_MAIN;
        const bool hn = (nt < NTILES);

        if (hn) {
            const float* ap = emb + (size_t)(nt * 64 + arow) * HH + aseg * 4;
            #pragma unroll
            for (int j = 0; j < 8; j++) ra[j] = *(const float4*)(ap + j * 32);
            if (tid < 64) {
                int m = nt * 64 + tid;
                brow[(cur ^ 1) * 64 + tid] = batch[m];
                wrow[(cur ^ 1) * 64 + tid] = (ntype[m] == 0) ? g_gate[m >> 2] : 1.0f;
            }
        }

        float acc[8][4];
        #pragma unroll
        for (int ni = 0; ni < 8; ni++)
            #pragma unroll
            for (int r = 0; r < 4; r++) acc[ni][r] = 0.0f;

        const uint32_t ab = a_lm + (uint32_t)(cur * A_STAGE);
        #pragma unroll
        for (int ks = 0; ks < 16; ks++) {
            uint32_t af[4];
            LDMX4(af[0], af[1], af[2], af[3], ab + ks * 32);
            uint32_t bf[4][4];
            #pragma unroll
            for (int nip = 0; nip < 4; nip++)
                LDMX4(bf[nip][0], bf[nip][1], bf[nip][2], bf[nip][3],
                      b_lm + nip * 8448 + ks * 32);
            #pragma unroll
            for (int ni = 0; ni < 8; ni++)
                MMA16816(acc[ni][0], acc[ni][1], acc[ni][2], acc[ni][3],
                         af[0], af[1], af[2], af[3],
                         bf[ni >> 1][(ni & 1) * 2], bf[ni >> 1][(ni & 1) * 2 + 1]);
        }

        if (hn) {
            uint32_t base = sbase + A_OFF + (uint32_t)((cur ^ 1) * A_STAGE)
                          + (uint32_t)((arow * 264 + aseg * 4) * 2);
            #pragma unroll
            for (int j = 0; j < 8; j++) {
                __half2 h0 = __float22half2_rn(make_float2(ra[j].x, ra[j].y));
                __half2 h1 = __float22half2_rn(make_float2(ra[j].z, ra[j].w));
                asm volatile("st.shared.v2.b32 [%0], {%1,%2};"
                             :: "r"(base + j * 64),
                                "r"(*(uint32_t*)&h0), "r"(*(uint32_t*)&h1) : "memory");
            }
        }

        // ---- epilogue: bias + gate, shuffle segment-reduce, atomics ----
        {
            const int l1 = wm * 16 + (lane >> 2);
            const int l2 = l1 + 8;
            const int*   br = brow + cur * 64;
            const float* wr = wrow + cur * 64;
            const float w1 = wr[l1], w2 = wr[l2];
            #pragma unroll
            for (int ni = 0; ni < 8; ni++) {
                int c = wn * 64 + ni * 8 + (lane & 3) * 2;
                float b0 = sbias[c], b1 = sbias[c + 1];
                acc[ni][0] = (acc[ni][0] + b0) * w1;
                acc[ni][1] = (acc[ni][1] + b1) * w1;
                acc[ni][2] = (acc[ni][2] + b0) * w2;
                acc[ni][3] = (acc[ni][3] + b1) * w2;
            }
            const int glo = br[wm * 16], ghi = br[wm * 16 + 15];
            const int bg1 = br[l1], bg2 = br[l2];
            for (int g = glo; g <= ghi; g++) {
                const bool p1 = (bg1 == g), p2 = (bg2 == g);
                #pragma unroll
                for (int ni = 0; ni < 8; ni++) {
                    float s0 = (p1 ? acc[ni][0] : 0.0f) + (p2 ? acc[ni][2] : 0.0f);
                    float s1 = (p1 ? acc[ni][1] : 0.0f) + (p2 ? acc[ni][3] : 0.0f);
                    float m0v = fmaxf(p1 ? acc[ni][0] : -INFINITY, p2 ? acc[ni][2] : -INFINITY);
                    float m1v = fmaxf(p1 ? acc[ni][1] : -INFINITY, p2 ? acc[ni][3] : -INFINITY);
                    #pragma unroll
                    for (int off = 4; off < 32; off <<= 1) {
                        s0  += __shfl_xor_sync(0xffffffffu, s0,  off);
                        s1  += __shfl_xor_sync(0xffffffffu, s1,  off);
                        m0v = fmaxf(m0v, __shfl_xor_sync(0xffffffffu, m0v, off));
                        m1v = fmaxf(m1v, __shfl_xor_sync(0xffffffffu, m1v, off));
                    }
                    if (lane < 4) {
                        int c = wn * 64 + ni * 8 + lane * 2;
                        atomicAdd(&g_sums[g * HH + c],     s0);
                        atomicAdd(&g_sums[g * HH + c + 1], s1);
                        if (m0v > -INFINITY) atomicMaxF(&g_maxs[g * HH + c],     m0v);
                        if (m1v > -INFINITY) atomicMaxF(&g_maxs[g * HH + c + 1], m1v);
                    }
                }
            }
        }
        __syncthreads();
    }
}

// ---------------- final linear ----------------
__global__ __launch_bounds__(256) void final_kernel(
    const float* __restrict__ Wpost,
    const float* __restrict__ bpost,
    float* __restrict__ out)
{
    __shared__ float comb[8][2 * HH];
    __shared__ float invc[8];
    int tid = threadIdx.x;
    int g0 = blockIdx.x * 8;

    if (tid < 8) {
        int g = g0 + tid;
        int c = g_start[g + 1] - g_start[g];
        invc[tid] = 1.0f / fmaxf((float)c, 1.0f);
    }
    __syncthreads();

    for (int idx = tid; idx < 8 * 2 * HH; idx += 256) {
        int g = idx >> 9;
        int k = idx & 511;
        float v;
        if (k < HH) {
            v = g_sums[(size_t)(g0 + g) * HH + k] * invc[g];
        } else {
            float m = g_maxs[(size_t)(g0 + g) * HH + (k - HH)];
            v = isfinite(m) ? m : 0.0f;
        }
        comb[g][k] = v;
    }
    __syncthreads();

    float acc[8];
    #pragma unroll
    for (int g = 0; g < 8; g++) acc[g] = 0.0f;

    for (int k = 0; k < 2 * HH; k++) {
        float wv = Wpost[(size_t)k * HH + tid];
        #pragma unroll
        for (int g = 0; g < 8; g++) acc[g] = fmaf(comb[g][k], wv, acc[g]);
    }
    float bb = bpost[tid];
    #pragma unroll
    for (int g = 0; g < 8; g++)
        out[(size_t)(g0 + g) * HH + tid] = acc[g] + bb;
}

// ---------------- launch ----------------
extern "C" void kernel_launch(void* const* d_in, const int* in_sizes, int n_in,
                              void* d_out, int out_size)
{
    const float* emb   = (const float*)d_in[0];
    const int*   batch = (const int*)  d_in[1];
    const float* props = (const float*)d_in[2];
    const int*   ntype = (const int*)  d_in[3];
    const float* Wpre  = (const float*)d_in[4];
    const float* bpre  = (const float*)d_in[5];
    const float* W1    = (const float*)d_in[6];
    const float* b1    = (const float*)d_in[7];
    const float* W2    = (const float*)d_in[8];
    const float* b2    = (const float*)d_in[9];
    const float* Wpost = (const float*)d_in[10];
    const float* bpost = (const float*)d_in[11];
    float* out = (float*)d_out;

    cudaFuncSetAttribute(main_kernel, cudaFuncAttributeMaxDynamicSharedMemorySize, SMEM_SZ);

    prep_kernel<<<256, 256>>>(props, W1, b1, W2, b2, Wpre, batch);
    main_kernel<<<GRID_MAIN, 512, SMEM_SZ>>>(emb, batch, ntype, bpre);
    final_kernel<<<NG / 8, 256>>>(Wpost, bpost, out);
}